// round 7
// baseline (speedup 1.0000x reference)
#include <cuda_runtime.h>

#define NN 50000
#define EE 800000
#define FD 128      // H*HID
#define EDD 16
#define HIDD 32
#define HH 4
#define OUTD 64
#define NEGS 0.1f

typedef unsigned long long ull;

// ---------------- scratch (device globals) -----------------------------------
__device__ float g_f0[NN * HIDD];
__device__ float g_f1[NN * HIDD];
__device__ float g_f2[NN * HIDD];
__device__ float g_xl[(size_t)NN * FD];
__device__ float g_xr[(size_t)NN * FD];
__device__ int   g_deg[NN];
__device__ int   g_cursor[NN];
__device__ int   g_row[NN + 1];
__device__ int   g_srcs[EE];
__device__ int   g_perm[EE];

__device__ __forceinline__ float lrelu(float v) { return fmaxf(v, NEGS * v); }
__device__ __forceinline__ void fma2(ull& acc, ull a, ull b) {
    asm("fma.rn.f32x2 %0, %1, %2, %0;" : "+l"(acc) : "l"(a), "l"(b));
}
__device__ __forceinline__ float2 upk(ull v) {
    float2 r; asm("mov.b64 {%0,%1}, %2;" : "=f"(r.x), "=f"(r.y) : "l"(v)); return r;
}

// ------ launch 0: zero deg + cursor -------------------------------------------
__global__ void k_zero() {
    int i = blockIdx.x * blockDim.x + threadIdx.x;
    if (i < NN) { g_deg[i] = 0; g_cursor[i] = 0; }
}

// ------ launch 1: embed (Linear+BN+LeakyReLU) + dst histogram side work -------
__global__ void k_embed_hist(const float* __restrict__ x, const float* __restrict__ W0,
                             const float* __restrict__ b0, const float* __restrict__ bng,
                             const float* __restrict__ bnb, const float* __restrict__ bnm,
                             const float* __restrict__ bnv, const int* __restrict__ ei) {
    __shared__ float W0t[128 * 32];   // [k][j]
    int tid = threadIdx.x;
    for (int i = tid; i < 128 * 32; i += blockDim.x) {
        int k = i >> 5, j = i & 31;
        W0t[i] = W0[j * 128 + k];
    }
    __syncthreads();
    int warp = tid >> 5, lane = tid & 31;
    float sc = bng[lane] * rsqrtf(bnv[lane] + 1e-5f);
    float bb = bnb[lane], bm = bnm[lane], b00 = b0[lane];
#pragma unroll
    for (int it = 0; it < 8; it++) {
        int n = blockIdx.x * 64 + it * 8 + warp;
        if (n < NN) {
            const float* xr_ = x + (size_t)n * 128;
            float acc = 0.f;
#pragma unroll 8
            for (int k = 0; k < 128; k++) acc += xr_[k] * W0t[k * 32 + lane];
            acc += b00;
            acc = (acc - bm) * sc + bb;
            g_f0[n * 32 + lane] = lrelu(acc);
        }
    }
    // histogram of dst degrees
    int gs = blockIdx.x * blockDim.x + tid;
    int stride = gridDim.x * blockDim.x;
    for (int e = gs; e < EE; e += stride) atomicAdd(&g_deg[ei[EE + e]], 1);
}

// ------ launch 2: exclusive scan of degrees -> g_row (single block) -----------
__global__ void k_scan() {
    __shared__ int wsum[32];
    __shared__ int carry;
    int tid = threadIdx.x, lane = tid & 31, w = tid >> 5;
    if (tid == 0) { carry = 0; g_row[0] = 0; }
    __syncthreads();
    for (int t0 = 0; t0 < NN; t0 += 1024) {
        int i = t0 + tid;
        int v = (i < NN) ? g_deg[i] : 0;
        int s = v;
#pragma unroll
        for (int o = 1; o < 32; o <<= 1) {
            int u = __shfl_up_sync(0xffffffffu, s, o);
            if (lane >= o) s += u;
        }
        if (lane == 31) wsum[w] = s;
        __syncthreads();
        if (w == 0) {
            int ws = wsum[lane];
#pragma unroll
            for (int o = 1; o < 32; o <<= 1) {
                int u = __shfl_up_sync(0xffffffffu, ws, o);
                if (lane >= o) ws += u;
            }
            wsum[lane] = ws;
        }
        __syncthreads();
        int inc = s + (w > 0 ? wsum[w - 1] : 0) + carry;
        if (i < NN) g_row[i + 1] = inc;
        __syncthreads();
        if (tid == 1023) carry = inc;
        __syncthreads();
    }
}

// ------ launch 3: scatter edges into CSR order --------------------------------
__global__ void k_scatter(const int* __restrict__ ei) {
    int e = blockIdx.x * blockDim.x + threadIdx.x;
    if (e >= EE) return;
    int dst = ei[EE + e];
    int pos = g_row[dst] + atomicAdd(&g_cursor[dst], 1);
    g_srcs[pos] = ei[e];
    g_perm[pos] = e;
}

// ------ node transforms (unchanged) -------------------------------------------
__global__ void k_xlxr(const float* __restrict__ feat,
                       const float* __restrict__ Wl, const float* __restrict__ bl,
                       const float* __restrict__ Wr, const float* __restrict__ br) {
    __shared__ float WlT[32 * 128];
    __shared__ float WrT[32 * 128];
    __shared__ float tile[32 * 32];
    int tid = threadIdx.x;
    for (int i = tid; i < 32 * 128; i += blockDim.x) {
        int k = i >> 7, j = i & 127;
        WlT[i] = Wl[j * 32 + k];
        WrT[i] = Wr[j * 32 + k];
    }
    int nbase = blockIdx.x * 32;
    for (int i = tid; i < 32 * 32; i += blockDim.x) {
        int n = nbase + (i >> 5);
        tile[i] = (n < NN) ? feat[n * 32 + (i & 31)] : 0.f;
    }
    __syncthreads();
    int j = tid & 127;
    int half = tid >> 7;
    float accl[16], accr[16];
#pragma unroll
    for (int n = 0; n < 16; n++) { accl[n] = 0.f; accr[n] = 0.f; }
#pragma unroll
    for (int k = 0; k < 32; k++) {
        float wl = WlT[k * 128 + j];
        float wr = WrT[k * 128 + j];
        const float* tr = &tile[(half * 16) * 32 + k];
#pragma unroll
        for (int n = 0; n < 16; n++) {
            float fv = tr[n * 32];
            accl[n] += fv * wl;
            accr[n] += fv * wr;
        }
    }
    float blj = bl[j], brj = br[j];
#pragma unroll
    for (int n = 0; n < 16; n++) {
        int node = nbase + half * 16 + n;
        if (node < NN) {
            g_xl[(size_t)node * 128 + j] = accl[n] + blj;
            g_xr[(size_t)node * 128 + j] = accr[n] + brj;
        }
    }
}

// ------ fused GAT layer: warp per node, alpha+softmax+aggregate in one pass ---
// lane owns channels 4*lane..4*lane+3 (head = lane>>3).
#define GAT_NPW 4
__global__ __launch_bounds__(256)
void k_gat(const float* __restrict__ eattr,
           const float* __restrict__ We, const float* __restrict__ att,
           const float* __restrict__ bias, float* __restrict__ out) {
    __shared__ float WeS[16 * 128];                  // [d][channel]
    __shared__ __align__(16) float2 evsp[8][8][18];  // [warp][edge][d] splat, padded
    int tid = threadIdx.x;
    for (int i = tid; i < 16 * 128; i += blockDim.x) {
        int d = i >> 7, j = i & 127;
        WeS[i] = We[j * 16 + d];
    }
    __syncthreads();
    int warp = tid >> 5, lane = tid & 31;
    int q = lane & 3, g = lane >> 2;
    float4 att4 = ((const float4*)att)[lane];
    float4 bias4 = make_float4(0.f, 0.f, 0.f, 0.f);
    if (lane < 8) bias4 = ((const float4*)bias)[lane];

    for (int t = 0; t < GAT_NPW; t++) {
        int n = (blockIdx.x * 8 + warp) * GAT_NPW + t;
        if (n >= NN) break;
        int rs = g_row[n], deg = g_row[n + 1] - rs;
        float4 xr4  = ((const float4*)(g_xr + (size_t)n * 128))[lane];
        float4 xls4 = ((const float4*)(g_xl + (size_t)n * 128))[lane];
        float4 num = make_float4(0.f, 0.f, 0.f, 0.f);
        float4 easum = make_float4(0.f, 0.f, 0.f, 0.f);
        float den = 0.f;

        for (int c0 = 0; c0 < deg; c0 += 8) {
            // stage eattr splats: lane -> edge g of chunk, dims 4q..4q+3
            float4 ea4 = make_float4(0.f, 0.f, 0.f, 0.f);
            if (c0 + g < deg) {
                int pe = g_perm[rs + c0 + g];
                ea4 = ((const float4*)eattr)[(size_t)pe * 4 + q];
            }
            easum.x += ea4.x; easum.y += ea4.y; easum.z += ea4.z; easum.w += ea4.w;
            {
                float2* myev = &evsp[warp][g][q * 4];
                myev[0] = make_float2(ea4.x, ea4.x);
                myev[1] = make_float2(ea4.y, ea4.y);
                myev[2] = make_float2(ea4.z, ea4.z);
                myev[3] = make_float2(ea4.w, ea4.w);
            }
            int sreg = n;
            if (lane < 8 && c0 + lane < deg) sreg = g_srcs[rs + c0 + lane];
            __syncwarp();

            ull acc01[8], acc23[8];
#pragma unroll
            for (int e = 0; e < 8; e++) { acc01[e] = 0ull; acc23[e] = 0ull; }
#pragma unroll
            for (int dp = 0; dp < 8; dp++) {
                ulonglong2 wa = *(const ulonglong2*)&WeS[(2 * dp) * 128 + 4 * lane];
                ulonglong2 wb = *(const ulonglong2*)&WeS[(2 * dp + 1) * 128 + 4 * lane];
#pragma unroll
                for (int e = 0; e < 8; e++) {
                    ulonglong2 ev = *(const ulonglong2*)&evsp[warp][e][2 * dp];
                    fma2(acc01[e], ev.x, wa.x);
                    fma2(acc23[e], ev.x, wa.y);
                    fma2(acc01[e], ev.y, wb.x);
                    fma2(acc23[e], ev.y, wb.y);
                }
            }
            int cnt = deg - c0; if (cnt > 8) cnt = 8;
#pragma unroll
            for (int e = 0; e < 8; e++) {
                if (e >= cnt) break;
                int se = __shfl_sync(0xffffffffu, sreg, e);
                float4 xl4 = ((const float4*)(g_xl + (size_t)se * 128))[lane];
                float2 a = upk(acc01[e]);
                float2 b = upk(acc23[e]);
                float t0 = lrelu(xl4.x + xr4.x + a.x) * att4.x;
                float t1 = lrelu(xl4.y + xr4.y + a.y) * att4.y;
                float t2 = lrelu(xl4.z + xr4.z + b.x) * att4.z;
                float t3 = lrelu(xl4.w + xr4.w + b.y) * att4.w;
                float s = (t0 + t1) + (t2 + t3);
                s += __shfl_xor_sync(0xffffffffu, s, 1);
                s += __shfl_xor_sync(0xffffffffu, s, 2);
                s += __shfl_xor_sync(0xffffffffu, s, 4);
                float ex = __expf(s);
                num.x += ex * xl4.x; num.y += ex * xl4.y;
                num.z += ex * xl4.z; num.w += ex * xl4.w;
                den += ex;
            }
            __syncwarp();
        }

        // self-loop: attr = mean of incoming eattr
        easum.x += __shfl_xor_sync(0xffffffffu, easum.x, 4);
        easum.y += __shfl_xor_sync(0xffffffffu, easum.y, 4);
        easum.z += __shfl_xor_sync(0xffffffffu, easum.z, 4);
        easum.w += __shfl_xor_sync(0xffffffffu, easum.w, 4);
        easum.x += __shfl_xor_sync(0xffffffffu, easum.x, 8);
        easum.y += __shfl_xor_sync(0xffffffffu, easum.y, 8);
        easum.z += __shfl_xor_sync(0xffffffffu, easum.z, 8);
        easum.w += __shfl_xor_sync(0xffffffffu, easum.w, 8);
        easum.x += __shfl_xor_sync(0xffffffffu, easum.x, 16);
        easum.y += __shfl_xor_sync(0xffffffffu, easum.y, 16);
        easum.z += __shfl_xor_sync(0xffffffffu, easum.z, 16);
        easum.w += __shfl_xor_sync(0xffffffffu, easum.w, 16);
        float invd = 1.f / fmaxf((float)deg, 1.f);
        if (lane < 4) {
            float2* myev = &evsp[warp][0][lane * 4];
            myev[0] = make_float2(easum.x * invd, easum.x * invd);
            myev[1] = make_float2(easum.y * invd, easum.y * invd);
            myev[2] = make_float2(easum.z * invd, easum.z * invd);
            myev[3] = make_float2(easum.w * invd, easum.w * invd);
        }
        __syncwarp();
        {
            ull a01 = 0ull, a23 = 0ull;
#pragma unroll
            for (int dp = 0; dp < 8; dp++) {
                ulonglong2 wa = *(const ulonglong2*)&WeS[(2 * dp) * 128 + 4 * lane];
                ulonglong2 wb = *(const ulonglong2*)&WeS[(2 * dp + 1) * 128 + 4 * lane];
                ulonglong2 ev = *(const ulonglong2*)&evsp[warp][0][2 * dp];
                fma2(a01, ev.x, wa.x);
                fma2(a23, ev.x, wa.y);
                fma2(a01, ev.y, wb.x);
                fma2(a23, ev.y, wb.y);
            }
            float2 a = upk(a01);
            float2 b = upk(a23);
            float t0 = lrelu(xls4.x + xr4.x + a.x) * att4.x;
            float t1 = lrelu(xls4.y + xr4.y + a.y) * att4.y;
            float t2 = lrelu(xls4.z + xr4.z + b.x) * att4.z;
            float t3 = lrelu(xls4.w + xr4.w + b.y) * att4.w;
            float s = (t0 + t1) + (t2 + t3);
            s += __shfl_xor_sync(0xffffffffu, s, 1);
            s += __shfl_xor_sync(0xffffffffu, s, 2);
            s += __shfl_xor_sync(0xffffffffu, s, 4);
            float ex = __expf(s);
            num.x += ex * xls4.x; num.y += ex * xls4.y;
            num.z += ex * xls4.z; num.w += ex * xls4.w;
            den += ex;
        }
        __syncwarp();

        // normalize per head, mean over heads, bias, store
        float r = 1.f / den;
        float4 p;
        p.x = num.x * r; p.y = num.y * r; p.z = num.z * r; p.w = num.w * r;
        p.x += __shfl_xor_sync(0xffffffffu, p.x, 8);
        p.y += __shfl_xor_sync(0xffffffffu, p.y, 8);
        p.z += __shfl_xor_sync(0xffffffffu, p.z, 8);
        p.w += __shfl_xor_sync(0xffffffffu, p.w, 8);
        p.x += __shfl_xor_sync(0xffffffffu, p.x, 16);
        p.y += __shfl_xor_sync(0xffffffffu, p.y, 16);
        p.z += __shfl_xor_sync(0xffffffffu, p.z, 16);
        p.w += __shfl_xor_sync(0xffffffffu, p.w, 16);
        if (lane < 8) {
            float4 o;
            o.x = 0.25f * p.x + bias4.x;
            o.y = 0.25f * p.y + bias4.y;
            o.z = 0.25f * p.z + bias4.z;
            o.w = 0.25f * p.w + bias4.w;
            ((float4*)(out + (size_t)n * 32))[lane] = o;
        }
    }
}

// ------ output head -------------------------------------------------------------
__global__ void k_final(const float* __restrict__ feat, const float* __restrict__ Wout,
                        const float* __restrict__ bout, float* __restrict__ y) {
    __shared__ float WT[32 * 64];   // [c][o]
    int tid = threadIdx.x;
    for (int i = tid; i < 32 * 64; i += blockDim.x) {
        int c = i >> 6, o = i & 63;
        WT[i] = Wout[o * 32 + c];
    }
    __syncthreads();
    int o = tid & 63;
    float bo = bout[o];
#pragma unroll
    for (int it = 0; it < 16; it++) {
        int n = blockIdx.x * 64 + it * 4 + (tid >> 6);
        if (n >= NN) return;
        const float* fr = feat + n * 32;
        float acc = 0.f;
#pragma unroll
        for (int c = 0; c < 32; c++) acc += fr[c] * WT[c * 64 + o];
        acc += bo;
        y[(size_t)n * 64 + o] = lrelu(acc);
    }
}

// =============================================================================
extern "C" void kernel_launch(void* const* d_in, const int* in_sizes, int n_in,
                              void* d_out, int out_size) {
    const float* x     = (const float*)d_in[0];
    const int*   ei    = (const int*)d_in[1];
    const float* eattr = (const float*)d_in[2];
    const float* W0    = (const float*)d_in[3];
    const float* b0    = (const float*)d_in[4];
    const float* bng   = (const float*)d_in[5];
    const float* bnb   = (const float*)d_in[6];
    const float* bnm   = (const float*)d_in[7];
    const float* bnv   = (const float*)d_in[8];
    const float* Wl[2]   = {(const float*)d_in[9],  (const float*)d_in[16]};
    const float* bl[2]   = {(const float*)d_in[10], (const float*)d_in[17]};
    const float* Wr[2]   = {(const float*)d_in[11], (const float*)d_in[18]};
    const float* br[2]   = {(const float*)d_in[12], (const float*)d_in[19]};
    const float* We[2]   = {(const float*)d_in[13], (const float*)d_in[20]};
    const float* att[2]  = {(const float*)d_in[14], (const float*)d_in[21]};
    const float* bias[2] = {(const float*)d_in[15], (const float*)d_in[22]};
    const float* Wout  = (const float*)d_in[23];
    const float* bout  = (const float*)d_in[24];
    float* y = (float*)d_out;

    float *f0, *f1, *f2;
    cudaGetSymbolAddress((void**)&f0, g_f0);
    cudaGetSymbolAddress((void**)&f1, g_f1);
    cudaGetSymbolAddress((void**)&f2, g_f2);

    k_zero<<<(NN + 255) / 256, 256>>>();                                             // 0
    k_embed_hist<<<(NN + 63) / 64, 256>>>(x, W0, b0, bng, bnb, bnm, bnv, ei);        // 1
    k_scan<<<1, 1024>>>();                                                           // 2
    k_scatter<<<(EE + 255) / 256, 256>>>(ei);                                        // 3 <- profiled

    const float* fin[2]  = {f0, f1};
    float*       fout[2] = {f1, f2};
    for (int l = 0; l < 2; l++) {
        k_xlxr<<<(NN + 31) / 32, 256>>>(fin[l], Wl[l], bl[l], Wr[l], br[l]);         // 4, 6
        k_gat<<<(NN + 8 * GAT_NPW - 1) / (8 * GAT_NPW), 256>>>(
            eattr, We[l], att[l], bias[l], fout[l]);                                 // 5, 7
    }
    k_final<<<(NN + 63) / 64, 256>>>(f2, Wout, bout, y);                             // 8
}